// round 1
// baseline (speedup 1.0000x reference)
#include <cuda_runtime.h>
#include <cuda_bf16.h>

// Problem constants (fixed by setup_inputs)
#define C_IN  128
#define D_OUT 256
#define IMG   64
#define R1    8
#define R2    4
#define CC    8     // input-channel chunk staged in smem per iteration

// Reconstructed weights, transposed for coalesced per-d loads: [c][tap(9)][d]
__device__ float g_Wt[C_IN * 9 * D_OUT];   // 1.18 MB

// ---------------------------------------------------------------------------
// Phase 1: rebuild W[d,c,kh,kw] = sum_{r,s} core0[d,c,r]*core1[d,r,kh,s]*core2[d,s,kw]
// One block per d (256 blocks, 128 threads). Contract s first (M[r,tap]), then r.
// ---------------------------------------------------------------------------
__global__ void build_w_kernel(const float* __restrict__ core0,
                               const float* __restrict__ core1,
                               const float* __restrict__ core2) {
    const int d = blockIdx.x;
    const int t = threadIdx.x;           // 128 threads
    __shared__ float M[R1 * 9];          // M[r][tap] = sum_s core1[d,r,kh,s]*core2[d,s,kw]

    if (t < R1 * 9) {
        const int r  = t / 9;
        const int kj = t % 9;
        const int kh = kj / 3, kw = kj % 3;
        float acc = 0.f;
        #pragma unroll
        for (int s = 0; s < R2; s++)
            acc += core1[((d * R1 + r) * 3 + kh) * R2 + s] * core2[(d * R2 + s) * 3 + kw];
        M[t] = acc;
    }
    __syncthreads();

    const int c = t;                     // one input channel per thread
    float a[R1];
    #pragma unroll
    for (int r = 0; r < R1; r++) a[r] = core0[(d * C_IN + c) * R1 + r];

    #pragma unroll
    for (int kj = 0; kj < 9; kj++) {
        float acc = 0.f;
        #pragma unroll
        for (int r = 0; r < R1; r++) acc += a[r] * M[r * 9 + kj];
        g_Wt[(c * 9 + kj) * D_OUT + d] = acc;
    }
}

// ---------------------------------------------------------------------------
// Phase 2: direct 3x3 conv, stride 1, pad 1 (cross-correlation, matches JAX).
// Block tile: 64 d-channels x 4 output rows x 64 cols (one n).
// Thread tile: 4 d x 16 w (256 threads = 16 d-groups x 16 spatial groups).
// x slab (CC chans x 6 rows x 66 cols w/ halo) + W chunk (CC x 9 x 64d) in smem.
// ---------------------------------------------------------------------------
__global__ __launch_bounds__(256)
void conv_kernel(const float* __restrict__ x,
                 const float* __restrict__ bias,
                 float* __restrict__ out) {
    const int n  = blockIdx.z;
    const int d0 = blockIdx.y * 64;
    const int h0 = blockIdx.x * 4;
    const int tid = threadIdx.x;
    const int td = tid & 15;          // d-group: channels d0 + td*4 .. +3
    const int ts = tid >> 4;          // spatial group 0..15
    const int hh = ts >> 2;           // local output row 0..3
    const int wq = (ts & 3) * 16;     // local output col base 0/16/32/48

    __shared__ float xs[CC][6][66];   // rows h0-1 .. h0+4, cols -1..64
    __shared__ float ws[CC][9][64];   // [c][tap][d]

    float acc[4][16];
    #pragma unroll
    for (int a = 0; a < 4; a++)
        #pragma unroll
        for (int b = 0; b < 16; b++) acc[a][b] = 0.f;

    for (int c0 = 0; c0 < C_IN; c0 += CC) {
        __syncthreads();
        // ---- stage x slab (zero-fill halo) ----
        for (int idx = tid; idx < CC * 6 * 66; idx += 256) {
            const int c   = idx / (6 * 66);
            const int rem = idx % (6 * 66);
            const int row = rem / 66;
            const int col = rem % 66;
            const int h_in = h0 - 1 + row;
            const int w_in = col - 1;
            float v = 0.f;
            if ((unsigned)h_in < (unsigned)IMG && (unsigned)w_in < (unsigned)IMG)
                v = x[((n * C_IN + c0 + c) * IMG + h_in) * IMG + w_in];
            xs[c][row][col] = v;
        }
        // ---- stage W chunk (coalesced over d) ----
        for (int idx = tid; idx < CC * 9 * 64; idx += 256) {
            const int dd = idx & 63;
            const int kj = (idx >> 6) % 9;
            const int c  = idx / (9 * 64);
            ws[c][kj][dd] = g_Wt[((c0 + c) * 9 + kj) * D_OUT + d0 + dd];
        }
        __syncthreads();

        #pragma unroll 1
        for (int c = 0; c < CC; c++) {
            #pragma unroll
            for (int kh = 0; kh < 3; kh++) {
                float xr[18];
                #pragma unroll
                for (int i = 0; i < 18; i++) xr[i] = xs[c][hh + kh][wq + i];
                #pragma unroll
                for (int kw = 0; kw < 3; kw++) {
                    const float4 w4 =
                        *reinterpret_cast<const float4*>(&ws[c][kh * 3 + kw][td * 4]);
                    #pragma unroll
                    for (int i = 0; i < 16; i++) {
                        const float xv = xr[i + kw];
                        acc[0][i] += w4.x * xv;
                        acc[1][i] += w4.y * xv;
                        acc[2][i] += w4.z * xv;
                        acc[3][i] += w4.w * xv;
                    }
                }
            }
        }
    }

    const float b = bias[0];
    const int h = h0 + hh;
    #pragma unroll
    for (int dd = 0; dd < 4; dd++) {
        const int d = d0 + td * 4 + dd;
        float* op = &out[((n * D_OUT + d) * IMG + h) * IMG + wq];
        #pragma unroll
        for (int i = 0; i < 16; i += 4) {
            float4 v = make_float4(acc[dd][i] + b, acc[dd][i + 1] + b,
                                   acc[dd][i + 2] + b, acc[dd][i + 3] + b);
            *reinterpret_cast<float4*>(op + i) = v;
        }
    }
}

// ---------------------------------------------------------------------------
// Inputs (metadata order): x, core0, core1, core2, bias, [stride=1, pad=1]
// ---------------------------------------------------------------------------
extern "C" void kernel_launch(void* const* d_in, const int* in_sizes, int n_in,
                              void* d_out, int out_size) {
    const float* x     = (const float*)d_in[0];
    const float* core0 = (const float*)d_in[1];
    const float* core1 = (const float*)d_in[2];
    const float* core2 = (const float*)d_in[3];
    const float* bias  = (const float*)d_in[4];
    float* out = (float*)d_out;

    build_w_kernel<<<D_OUT, C_IN>>>(core0, core1, core2);
    conv_kernel<<<dim3(IMG / 4, D_OUT / 64, 32), 256>>>(x, bias, out);
}

// round 4
// speedup vs baseline: 3.2825x; 3.2825x over previous
#include <cuda_runtime.h>
#include <cstdint>

// Problem constants
#define C_IN   128
#define D_OUT  256
#define IMG    64
#define R1     8
#define R2     4
#define KC     32          // input channels per K-chunk
#define NIT    36          // 4 c-chunks * 9 taps
#define TH     2           // output rows per CTA (M = 2*64 = 128)

// SMEM word-layout (fp32/tf32 words)
#define SLAB_POS     264               // 4 rows * 66 cols
#define SLAB_STRIDE  33                // 32 channels + 1 pad word (bank decorrelation)
#define SLAB_WORDS   (SLAB_POS * SLAB_STRIDE)      // 8712
#define B_STRIDE     264               // 256 d + 8 pad words
#define B_WORDS      (KC * B_STRIDE)               // 8448
#define SM_B0        SLAB_WORDS
#define SM_B1        (SM_B0 + B_WORDS)
#define SM_TOTALW    (SM_B1 + B_WORDS)             // 25608 words = 102432 B

// Reconstructed weights (tf32-rounded), laid out [tap][c][d]
__device__ float g_Wtap[9 * C_IN * D_OUT];

__device__ __forceinline__ uint32_t f2tf32(float f) {
    uint32_t r;
    asm("cvt.rna.tf32.f32 %0, %1;" : "=r"(r) : "f"(f));
    return r;
}

__device__ __forceinline__ void mma_tf32(float* d, const uint32_t* a, const uint32_t* b) {
    asm volatile(
        "mma.sync.aligned.m16n8k8.row.col.f32.tf32.tf32.f32 "
        "{%0,%1,%2,%3}, {%4,%5,%6,%7}, {%8,%9}, {%0,%1,%2,%3};"
        : "+f"(d[0]), "+f"(d[1]), "+f"(d[2]), "+f"(d[3])
        : "r"(a[0]), "r"(a[1]), "r"(a[2]), "r"(a[3]), "r"(b[0]), "r"(b[1]));
}

__device__ __forceinline__ void cp_async16(uint32_t saddr, const void* gptr) {
    asm volatile("cp.async.ca.shared.global [%0], [%1], 16;" :: "r"(saddr), "l"(gptr));
}

// ---------------------------------------------------------------------------
// Phase 1: W[d,c,kh,kw] = sum_{r,s} core0[d,c,r]*core1[d,r,kh,s]*core2[d,s,kw]
// stored tf32-rounded as g_Wtap[tap][c][d]
// ---------------------------------------------------------------------------
__global__ void build_w_kernel(const float* __restrict__ core0,
                               const float* __restrict__ core1,
                               const float* __restrict__ core2) {
    const int d = blockIdx.x;
    const int t = threadIdx.x;           // 128
    __shared__ float M[R1 * 9];
    if (t < R1 * 9) {
        const int r = t / 9, kj = t % 9, kh = kj / 3, kw = kj % 3;
        float acc = 0.f;
        #pragma unroll
        for (int s = 0; s < R2; s++)
            acc += core1[((d * R1 + r) * 3 + kh) * R2 + s] * core2[(d * R2 + s) * 3 + kw];
        M[t] = acc;
    }
    __syncthreads();
    const int c = t;
    float a[R1];
    #pragma unroll
    for (int r = 0; r < R1; r++) a[r] = core0[(d * C_IN + c) * R1 + r];
    #pragma unroll
    for (int kj = 0; kj < 9; kj++) {
        float acc = 0.f;
        #pragma unroll
        for (int r = 0; r < R1; r++) acc += a[r] * M[r * 9 + kj];
        const uint32_t tf = f2tf32(acc);
        g_Wtap[(kj * C_IN + c) * D_OUT + d] = __uint_as_float(tf);
    }
}

// ---------------------------------------------------------------------------
// Phase 2: tf32 mma.sync implicit GEMM.
// CTA: 128 M (2 rows x 64 cols) x 256 N (all d). 8 warps = 2(M) x 4(N),
// warp tile 64x64 via m16n8k8: 4 m-frags x 8 n-frags.
// K loop: 4 c-chunks x 9 taps x 4 ksteps(K=8).
// A frags read straight from the halo'd slab (im2col = addressing).
// B double-buffered via cp.async.
// ---------------------------------------------------------------------------
__global__ __launch_bounds__(256, 1)
void conv_mma_kernel(const float* __restrict__ x,
                     const float* __restrict__ bias,
                     float* __restrict__ out) {
    extern __shared__ uint32_t smw[];
    uint32_t* const slab = smw;               // [pos][33]
    const int tid = threadIdx.x;
    const int wid = tid >> 5;
    const int lane = tid & 31;
    const int g = lane >> 2;                  // groupID
    const int q = lane & 3;                   // threadID_in_group
    const int warp_m = wid & 1;               // 0..1
    const int warp_n = wid >> 1;              // 0..3
    const int n  = blockIdx.y;
    const int h0 = blockIdx.x * TH;

    uint32_t smem_base;
    asm("{ .reg .u64 t; cvta.to.shared.u64 t, %1; cvt.u32.u64 %0, t; }"
        : "=r"(smem_base) : "l"((void*)smw));

    float acc[4][8][4];
    #pragma unroll
    for (int i = 0; i < 4; i++)
        #pragma unroll
        for (int j = 0; j < 8; j++)
            #pragma unroll
            for (int k = 0; k < 4; k++) acc[i][j][k] = 0.f;

    // ---- staging helpers ----
    auto stage_slab = [&](int c0) {
        // slab[pos][perm(c)] = tf32(x[n][c0+c][h0-1+r][col-1]), zero halo
        for (int idx = tid; idx < KC * SLAB_POS; idx += 256) {
            const int c   = idx / SLAB_POS;
            const int pos = idx % SLAB_POS;
            const int r   = pos / 66;
            const int col = pos % 66;
            const int h_in = h0 - 1 + r;
            const int w_in = col - 1;
            float v = 0.f;
            if ((unsigned)h_in < (unsigned)IMG && (unsigned)w_in < (unsigned)IMG)
                v = x[((n * C_IN + c0 + c) * IMG + h_in) * IMG + w_in];
            const int cp = (c & 3) * 8 + (c >> 2);
            slab[pos * SLAB_STRIDE + cp] = f2tf32(v);
        }
    };
    auto issue_B = [&](int it, int buf) {
        const int c0  = (it / 9) * KC;
        const int tap = it % 9;
        const uint32_t sbase = smem_base + (SM_B0 + buf * B_WORDS) * 4;
        const float* gbase = g_Wtap + (size_t)tap * C_IN * D_OUT + (size_t)c0 * D_OUT;
        #pragma unroll
        for (int t = 0; t < 8; t++) {
            const int i4 = tid + t * 256;       // 0..2047 float4s
            const int c  = i4 >> 6;
            const int d4 = i4 & 63;
            cp_async16(sbase + (c * B_STRIDE + d4 * 4) * 4,
                       gbase + c * D_OUT + d4 * 4);
        }
        asm volatile("cp.async.commit_group;" ::: "memory");
    };

    // ---- prologue ----
    issue_B(0, 0);
    stage_slab(0);

    for (int it = 0; it < NIT; it++) {
        const int tap = it % 9;
        const int kh = tap / 3, kw = tap % 3;
        const uint32_t* const B = smw + SM_B0 + (it & 1) * B_WORDS;

        if (it + 1 < NIT) {
            issue_B(it + 1, (it + 1) & 1);
            asm volatile("cp.async.wait_group 1;" ::: "memory");
        } else {
            asm volatile("cp.async.wait_group 0;" ::: "memory");
        }
        __syncthreads();
        if (it > 0 && tap == 0) {
            stage_slab((it / 9) * KC);
            __syncthreads();
        }

        // ---- 4 ksteps of K=8 ----
        const int posA = (warp_m + kh) * 66 + g + kw;   // + i*16 (+8 for upper rows)
        #pragma unroll
        for (int ks = 0; ks < 4; ks++) {
            uint32_t a[4][4];
            #pragma unroll
            for (int i = 0; i < 4; i++) {
                const int w0 = (posA + i * 16) * SLAB_STRIDE + q * 8 + ks * 2;
                a[i][0] = slab[w0];
                a[i][2] = slab[w0 + 1];
                const int w1 = w0 + 8 * SLAB_STRIDE;
                a[i][1] = slab[w1];
                a[i][3] = slab[w1 + 1];
            }
            uint32_t b[8][2];
            #pragma unroll
            for (int j = 0; j < 8; j++) {
                const int w0 = (ks * 8 + q) * B_STRIDE + warp_n * 64 + j * 8 + g;
                b[j][0] = B[w0];
                b[j][1] = B[w0 + 4 * B_STRIDE];
            }
            #pragma unroll
            for (int i = 0; i < 4; i++)
                #pragma unroll
                for (int j = 0; j < 8; j++)
                    mma_tf32(acc[i][j], a[i], b[j]);
        }
        __syncthreads();   // B buffer reuse + slab overwrite protection
    }

    // ---- epilogue: acc -> out[n][d][h][w] + bias ----
    const float bval = bias[0];
    const int h = h0 + warp_m;
    #pragma unroll
    for (int i = 0; i < 4; i++) {
        const int w0 = i * 16 + g;
        #pragma unroll
        for (int j = 0; j < 8; j++) {
            const int d = warp_n * 64 + j * 8 + 2 * q;
            float* p0 = out + (((size_t)n * D_OUT + d) * IMG + h) * IMG;
            float* p1 = p0 + (size_t)IMG * IMG;       // d+1
            p0[w0]     = acc[i][j][0] + bval;
            p1[w0]     = acc[i][j][1] + bval;
            p0[w0 + 8] = acc[i][j][2] + bval;
            p1[w0 + 8] = acc[i][j][3] + bval;
        }
    }
}

// ---------------------------------------------------------------------------
// Inputs (metadata order): x, core0, core1, core2, bias, [stride, pad]
// ---------------------------------------------------------------------------
extern "C" void kernel_launch(void* const* d_in, const int* in_sizes, int n_in,
                              void* d_out, int out_size) {
    const float* x     = (const float*)d_in[0];
    const float* core0 = (const float*)d_in[1];
    const float* core1 = (const float*)d_in[2];
    const float* core2 = (const float*)d_in[3];
    const float* bias  = (const float*)d_in[4];
    float* out = (float*)d_out;

    build_w_kernel<<<D_OUT, C_IN>>>(core0, core1, core2);

    const int smem_bytes = SM_TOTALW * 4;
    cudaFuncSetAttribute(conv_mma_kernel, cudaFuncAttributeMaxDynamicSharedMemorySize, smem_bytes);
    conv_mma_kernel<<<dim3(IMG / TH, 32), 256, smem_bytes>>>(x, bias, out);
}